// round 16
// baseline (speedup 1.0000x reference)
#include <cuda_runtime.h>
#include <cuda_fp16.h>
#include <cstdint>

#define MAX_N 50000

// ---------------- device scratch (no allocation allowed) -------------------
// g_Yh row layout (1024 halfs): [Y0 | Y3 | Y1 | Y2]
//   fwd edge: Y0[f] + Y1[t];  rev edge: Y2[t] + Y3[f]   (biases folded)
__device__ __half g_Yh[(size_t)MAX_N * 1024];  // 102.4 MB, fits L2
__device__ float  g_agg[(size_t)MAX_N * 256];  // [N][256] aggregation
__device__ __half g_w2[2][65536];              // [dir][n*256+k] fp16 W2

// ---------------- small asm helpers ----------------------------------------
__device__ __forceinline__ uint32_t smem_u32(const void* p) {
    uint32_t a;
    asm("{ .reg .u64 t; cvta.to.shared.u64 t, %1; cvt.u32.u64 %0, t; }" : "=r"(a) : "l"(p));
    return a;
}
__device__ __forceinline__ void cpa16(uint32_t dst, const void* src) {
    asm volatile("cp.async.cg.shared.global [%0], [%1], 16;" :: "r"(dst), "l"(src));
}
#define CP_COMMIT() asm volatile("cp.async.commit_group;" ::: "memory")
#define CP_WAIT(n)  asm volatile("cp.async.wait_group %0;" :: "n"(n) : "memory")

__device__ __forceinline__ void ldsm4(uint32_t* r, uint32_t addr) {
    asm volatile("ldmatrix.sync.aligned.m8n8.x4.shared.b16 {%0,%1,%2,%3}, [%4];"
                 : "=r"(r[0]), "=r"(r[1]), "=r"(r[2]), "=r"(r[3]) : "r"(addr));
}
__device__ __forceinline__ void ldsm2(uint32_t* r, uint32_t addr) {
    asm volatile("ldmatrix.sync.aligned.m8n8.x2.shared.b16 {%0,%1}, [%2];"
                 : "=r"(r[0]), "=r"(r[1]) : "r"(addr));
}
__device__ __forceinline__ void mma16816(float* c, const uint32_t* a, const uint32_t* b) {
    asm volatile("mma.sync.aligned.m16n8k16.row.col.f32.f16.f16.f32 "
                 "{%0,%1,%2,%3}, {%4,%5,%6,%7}, {%8,%9}, {%0,%1,%2,%3};"
                 : "+f"(c[0]), "+f"(c[1]), "+f"(c[2]), "+f"(c[3])
                 : "r"(a[0]), "r"(a[1]), "r"(a[2]), "r"(a[3]), "r"(b[0]), "r"(b[1]));
}
__device__ __forceinline__ void red2(float* p, float x, float y) {
    asm volatile("red.global.add.v2.f32 [%0], {%1,%2};" :: "l"(p), "f"(x), "f"(y) : "memory");
}
__device__ __forceinline__ uint32_t f2h(float a, float b) {
    __half2 h = __floats2half2_rn(a, b);
    return *reinterpret_cast<uint32_t*>(&h);
}
// combine: relu(a + b + ef*w) in half2
__device__ __forceinline__ uint32_t cmb(uint32_t a, uint32_t b, uint32_t w, __half2 ef2) {
    __half2 s = __hadd2(*reinterpret_cast<__half2*>(&a), *reinterpret_cast<__half2*>(&b));
    s = __hfma2(ef2, *reinterpret_cast<__half2*>(&w), s);
    __half2 z = __floats2half2_rn(0.f, 0.f);
    s = __hmax2(s, z);
    return *reinterpret_cast<uint32_t*>(&s);
}

// ---------------- persistent edge-kernel smem layout (bytes) ----------------
#define SH    0            // [128 rows][264 halfs] hidden (stride 528B) = 67,584B
#define SW2   67584        // [256 n][264 halfs] W2 resident = 135,168B -> 202,752
#define SBIAS 202752       // 256 f32 -> 203,776
#define SWEFH 203776       // 256 half -> 204,288
#define ESMEM 204288

// ---------------- prep: W2 transpose + fp16 round ---------------------------
__global__ void prep_w_kernel(const float* __restrict__ W, __half* __restrict__ oh) {
    int i = blockIdx.x * 256 + threadIdx.x;      // i = n*256 + k
    if (i >= 65536) return;
    int n = i >> 8, k = i & 255;
    oh[i] = __float2half_rn(W[k * 256 + n]);
}

__global__ void zero_agg_kernel(int n4) {
    float4* p = reinterpret_cast<float4*>(g_agg);
    int i = blockIdx.x * blockDim.x + threadIdx.x;
    int stride = gridDim.x * blockDim.x;
    float4 z = make_float4(0.f, 0.f, 0.f, 0.f);
    for (; i < n4; i += stride) p[i] = z;
}

// ---------------- node-level L1 precompute (exact fp32 FFMA -> fp16) --------
__global__ __launch_bounds__(256, 2)
void precompute_y(const float* __restrict__ ns,
                  const float* __restrict__ W1, const float* __restrict__ RW1,
                  const float* __restrict__ b1, const float* __restrict__ Rb1, int N)
{
    extern __shared__ float sm[];
    float* sS = sm;           // 64*128
    float* sW = sm + 8192;    // 32*256
    const int tid = threadIdx.x;
    const int n0 = blockIdx.x * 64;

    for (int t = tid; t < 64 * 32; t += 256) {
        int n = t >> 5, c = t & 31;
        float4 v = make_float4(0.f, 0.f, 0.f, 0.f);
        if (n0 + n < N)
            v = reinterpret_cast<const float4*>(ns)[(size_t)(n0 + n) * 32 + c];
        reinterpret_cast<float4*>(sS)[t] = v;
    }

    const int wg = tid >> 5, lane = tid & 31;
    const int nb = wg * 8, j0 = lane * 8;

    for (int q = 0; q < 4; ++q) {
        const float* Wsrc = (q < 2) ? W1 : RW1;
        const int rowoff = (q & 1) * 128;
        const int seg = (q == 0) ? 0 : (q == 1) ? 2 : (q == 2) ? 3 : 1;
        float acc[8][8];
        #pragma unroll
        for (int jj = 0; jj < 8; ++jj) {
            float bv = (q == 1) ? b1[j0 + jj] : ((q == 3) ? Rb1[j0 + jj] : 0.f);
            #pragma unroll
            for (int ii = 0; ii < 8; ++ii) acc[ii][jj] = bv;
        }
        for (int kt = 0; kt < 4; ++kt) {
            __syncthreads();
            {
                const float4* src = reinterpret_cast<const float4*>(Wsrc + (rowoff + kt * 32) * 256);
                float4* dw = reinterpret_cast<float4*>(sW);
                #pragma unroll
                for (int t0 = 0; t0 < 8; ++t0) dw[tid + t0 * 256] = src[tid + t0 * 256];
            }
            __syncthreads();
            #pragma unroll 8
            for (int kk = 0; kk < 32; ++kk) {
                float xv[8];
                #pragma unroll
                for (int ii = 0; ii < 8; ++ii) xv[ii] = sS[(nb + ii) * 128 + kt * 32 + kk];
                float4 w0 = *reinterpret_cast<const float4*>(&sW[kk * 256 + j0]);
                float4 w1 = *reinterpret_cast<const float4*>(&sW[kk * 256 + j0 + 4]);
                float wv[8] = {w0.x, w0.y, w0.z, w0.w, w1.x, w1.y, w1.z, w1.w};
                #pragma unroll
                for (int ii = 0; ii < 8; ++ii)
                    #pragma unroll
                    for (int jj = 0; jj < 8; ++jj)
                        acc[ii][jj] = fmaf(xv[ii], wv[jj], acc[ii][jj]);
            }
        }
        #pragma unroll
        for (int ii = 0; ii < 8; ++ii) {
            int n = n0 + nb + ii;
            if (n < N) {
                uint4 pk;
                pk.x = f2h(acc[ii][0], acc[ii][1]);
                pk.y = f2h(acc[ii][2], acc[ii][3]);
                pk.z = f2h(acc[ii][4], acc[ii][5]);
                pk.w = f2h(acc[ii][6], acc[ii][7]);
                *reinterpret_cast<uint4*>(g_Yh + (size_t)n * 1024 + seg * 256 + j0) = pk;
            }
        }
    }
}

// ---------------- persistent edge kernel: one direction, W2 resident --------
// Tile loop: combine -> sync -> MMA (sync-free) -> sync -> scatter (no sync:
// scatter never touches sH, so it overlaps the next tile's combine).
__global__ __launch_bounds__(512, 1)
void edge_mma_kernel(const float* __restrict__ ef,
                     const int* __restrict__ fidx, const int* __restrict__ tidx,
                     const float* __restrict__ W1base,   // W1 or RW1 (ef column)
                     const float* __restrict__ bias2,
                     int dir, int E)
{
    extern __shared__ float smf[];
    char* smc = reinterpret_cast<char*>(smf);
    const uint32_t smb = smem_u32(smf);
    const int tid = threadIdx.x;
    const int wid = tid >> 5, lane = tid & 31;
    const int wm = wid & 3, wn = wid >> 2;       // 4 m-warps x 4 n-warps
    const int m0 = wm * 32, n0 = wn * 64;        // warp tile 32 x 64

    float*  sBias = reinterpret_cast<float*>(smc + SBIAS);
    __half* sWefH = reinterpret_cast<__half*>(smc + SWEFH);

    // ---- one-time: W2[dir] -> smem (256 n-rows x 256 halfs, stride 528B) ---
    {
        const __half* gw = g_w2[dir];
        #pragma unroll
        for (int t0 = 0; t0 < 16; ++t0) {
            int idx = t0 * 512 + tid;            // 8192 x 16B
            int n = idx >> 5, seg = idx & 31;
            cpa16(smb + SW2 + (uint32_t)(n * 528 + seg * 16), gw + n * 256 + seg * 8);
        }
        CP_COMMIT();
        if (tid < 256) {
            sBias[tid] = bias2[tid];
            sWefH[tid] = __float2half_rn(W1base[65536 + tid]);  // ef column
        }
        CP_WAIT(0);
        __syncthreads();
    }

    // lane-resolved fragment addresses
    const int rA = (lane & 7) + ((lane >> 3) & 1) * 8;
    const int cAo = (lane >> 4) * 8;
    const uint32_t aB0 = smb + SH + (uint32_t)((m0 + rA) * 528 + cAo * 2);
    const uint32_t aB1 = aB0 + 16 * 528;         // +16 rows
    const uint32_t bB = smb + SW2 +
        (uint32_t)((n0 + (lane & 7)) * 528 + ((lane >> 3) & 1) * 16);
    const int r0 = m0 + (lane >> 2);

    // combine-phase indices: 128 rows x 4 col-quarters (64 halfs each)
    const int crow = tid >> 2, cq = tid & 3;
    const uint4* W4 = reinterpret_cast<const uint4*>(sWefH + cq * 64);

    // bias accumulator init values (read once)
    float bv[8][2];
    #pragma unroll
    for (int nf = 0; nf < 8; ++nf) {
        int cc = n0 + nf * 8 + (lane & 3) * 2;
        bv[nf][0] = bias2[cc];
        bv[nf][1] = bias2[cc + 1];
    }

    const int nTiles = (E + 127) >> 7;
    for (int tile = blockIdx.x; tile < nTiles; tile += gridDim.x) {
        const int e0 = tile * 128;

        // ---- L1 combine (half2): h = relu(Ya + Yb + ef*wef) -> sH -----------
        {
            int ce = e0 + crow; if (ce >= E) ce = E - 1;
            const int cf = fidx[ce], ct = tidx[ce];
            const __half* Ap;
            const __half* Bp;
            if (dir == 0) {   // fwd: Y0[f] + Y1[t]
                Ap = g_Yh + (size_t)cf * 1024 + cq * 64;
                Bp = g_Yh + (size_t)ct * 1024 + 512 + cq * 64;
            } else {          // rev: Y2[t] + Y3[f]
                Ap = g_Yh + (size_t)ct * 1024 + 768 + cq * 64;
                Bp = g_Yh + (size_t)cf * 1024 + 256 + cq * 64;
            }
            const __half2 ef2 = __float2half2_rn(ef[ce]);
            const uint4* A4 = reinterpret_cast<const uint4*>(Ap);
            const uint4* B4 = reinterpret_cast<const uint4*>(Bp);
            #pragma unroll
            for (int i = 0; i < 8; ++i) {
                uint4 ua = A4[i], ub = B4[i], uw = W4[i];
                uint4 pk;
                pk.x = cmb(ua.x, ub.x, uw.x, ef2);
                pk.y = cmb(ua.y, ub.y, uw.y, ef2);
                pk.z = cmb(ua.z, ub.z, uw.z, ef2);
                pk.w = cmb(ua.w, ub.w, uw.w, ef2);
                *reinterpret_cast<uint4*>(smc + SH + crow * 528 + (cq * 64 + i * 8) * 2) = pk;
            }
        }
        __syncthreads();                          // sH visible to ldmatrix

        // ---- L2: msg = h @ W2 + b2 — fully sync-free -------------------------
        float acc0[8][4], acc1[8][4];
        #pragma unroll
        for (int nf = 0; nf < 8; ++nf) {
            acc0[nf][0] = bv[nf][0]; acc0[nf][1] = bv[nf][1];
            acc0[nf][2] = bv[nf][0]; acc0[nf][3] = bv[nf][1];
            acc1[nf][0] = bv[nf][0]; acc1[nf][1] = bv[nf][1];
            acc1[nf][2] = bv[nf][0]; acc1[nf][3] = bv[nf][1];
        }
        #pragma unroll 4
        for (int ks = 0; ks < 16; ++ks) {
            uint32_t A0[4], A1[4];
            ldsm4(A0, aB0 + ks * 32);
            ldsm4(A1, aB1 + ks * 32);
            const uint32_t wk = bB + ks * 32;
            #pragma unroll
            for (int nf = 0; nf < 8; ++nf) {
                uint32_t Bh[2];
                ldsm2(Bh, wk + nf * 4224);        // +8 n-rows = 8*528B
                mma16816(acc0[nf], A0, Bh);
                mma16816(acc1[nf], A1, Bh);
            }
        }
        __syncthreads();                          // all sH reads done

        // ---- scatter (overlaps next tile's combine; never touches sH) -------
        {
            const int* iD = dir ? fidx : tidx;
            const int e00 = e0 + r0;
            const int e08 = e00 + 8, e16 = e00 + 16, e24 = e00 + 24;
            const int d00 = (e00 < E) ? iD[e00] : 0;
            const int d08 = (e08 < E) ? iD[e08] : 0;
            const int d16 = (e16 < E) ? iD[e16] : 0;
            const int d24 = (e24 < E) ? iD[e24] : 0;
            float* p00 = g_agg + (size_t)d00 * 256;
            float* p08 = g_agg + (size_t)d08 * 256;
            float* p16 = g_agg + (size_t)d16 * 256;
            float* p24 = g_agg + (size_t)d24 * 256;
            #pragma unroll
            for (int nf = 0; nf < 8; ++nf) {
                int cc = n0 + nf * 8 + (lane & 3) * 2;
                if (e00 < E) red2(p00 + cc, acc0[nf][0], acc0[nf][1]);
                if (e08 < E) red2(p08 + cc, acc0[nf][2], acc0[nf][3]);
                if (e16 < E) red2(p16 + cc, acc1[nf][0], acc1[nf][1]);
                if (e24 < E) red2(p24 + cc, acc1[nf][2], acc1[nf][3]);
            }
        }
        // no barrier: next combine only writes sH, already fenced by post-MMA sync
    }
}

// ---------------- node update MLP + residual (FFMA, 256 thr, 2 CTA/SM) -----
__global__ __launch_bounds__(256, 2)
void node_kernel(const float* __restrict__ node_states,
                 const float* __restrict__ Wn1, const float* __restrict__ bn1,
                 const float* __restrict__ Wn2, const float* __restrict__ bn2,
                 float* __restrict__ out, int N)
{
    extern __shared__ float sm[];
    float* sA = sm;            // 64*256
    float* sS = sm + 16384;    // 64*128
    float* sH = sm + 24576;    // 64*256
    float* sW = sm + 40960;    // 32*256

    const int tid = threadIdx.x;
    const int n0  = blockIdx.x * 64;

    for (int t = tid; t < 64 * 64; t += 256) {
        int n = t >> 6, c = t & 63;
        float4 v = make_float4(0.f, 0.f, 0.f, 0.f);
        if (n0 + n < N)
            v = reinterpret_cast<const float4*>(g_agg)[(size_t)(n0 + n) * 64 + c];
        reinterpret_cast<float4*>(sA)[t] = v;
    }
    for (int t = tid; t < 64 * 32; t += 256) {
        int n = t >> 5, c = t & 31;
        float4 v = make_float4(0.f, 0.f, 0.f, 0.f);
        if (n0 + n < N)
            v = reinterpret_cast<const float4*>(node_states)[(size_t)(n0 + n) * 32 + c];
        reinterpret_cast<float4*>(sS)[t] = v;
    }
    __syncthreads();

    const int wg = tid >> 5, lane = tid & 31;
    const int nBase = wg * 8, j0 = lane * 8;

    float acc[8][8];
    #pragma unroll
    for (int jj = 0; jj < 8; ++jj) {
        float bv = bn1[j0 + jj];
        #pragma unroll
        for (int ii = 0; ii < 8; ++ii) acc[ii][jj] = bv;
    }
    for (int kt = 0; kt < 12; ++kt) {
        __syncthreads();
        {
            const float4* src = reinterpret_cast<const float4*>(Wn1 + kt * 32 * 256);
            float4* dw = reinterpret_cast<float4*>(sW);
            #pragma unroll
            for (int t0 = 0; t0 < 8; ++t0) dw[tid + t0 * 256] = src[tid + t0 * 256];
        }
        __syncthreads();
        const float* Xb; int strd;
        if (kt < 8) { Xb = sA + kt * 32;       strd = 256; }
        else        { Xb = sS + (kt - 8) * 32; strd = 128; }
        #pragma unroll 8
        for (int kk = 0; kk < 32; ++kk) {
            float xv[8];
            #pragma unroll
            for (int ii = 0; ii < 8; ++ii) xv[ii] = Xb[(nBase + ii) * strd + kk];
            float4 w0 = *reinterpret_cast<const float4*>(&sW[kk * 256 + j0]);
            float4 w1 = *reinterpret_cast<const float4*>(&sW[kk * 256 + j0 + 4]);
            float wv[8] = {w0.x, w0.y, w0.z, w0.w, w1.x, w1.y, w1.z, w1.w};
            #pragma unroll
            for (int ii = 0; ii < 8; ++ii)
                #pragma unroll
                for (int jj = 0; jj < 8; ++jj)
                    acc[ii][jj] = fmaf(xv[ii], wv[jj], acc[ii][jj]);
        }
    }
    #pragma unroll
    for (int ii = 0; ii < 8; ++ii) {
        float4 h0 = make_float4(fmaxf(acc[ii][0], 0.f), fmaxf(acc[ii][1], 0.f),
                                fmaxf(acc[ii][2], 0.f), fmaxf(acc[ii][3], 0.f));
        float4 h1 = make_float4(fmaxf(acc[ii][4], 0.f), fmaxf(acc[ii][5], 0.f),
                                fmaxf(acc[ii][6], 0.f), fmaxf(acc[ii][7], 0.f));
        *reinterpret_cast<float4*>(&sH[(nBase + ii) * 256 + j0])     = h0;
        *reinterpret_cast<float4*>(&sH[(nBase + ii) * 256 + j0 + 4]) = h1;
    }

    const int j4 = lane * 4;
    float acc2[8][4];
    #pragma unroll
    for (int jj = 0; jj < 4; ++jj) {
        float bv = bn2[j4 + jj];
        #pragma unroll
        for (int ii = 0; ii < 8; ++ii) acc2[ii][jj] = bv;
    }
    for (int kt = 0; kt < 8; ++kt) {
        __syncthreads();
        {
            const float4* src = reinterpret_cast<const float4*>(Wn2 + kt * 32 * 128);
            float4* dw = reinterpret_cast<float4*>(sW);
            #pragma unroll
            for (int t0 = 0; t0 < 4; ++t0) dw[tid + t0 * 256] = src[tid + t0 * 256];
        }
        __syncthreads();
        #pragma unroll 8
        for (int kk = 0; kk < 32; ++kk) {
            float xv[8];
            #pragma unroll
            for (int ii = 0; ii < 8; ++ii) xv[ii] = sH[(nBase + ii) * 256 + kt * 32 + kk];
            float4 w = *reinterpret_cast<const float4*>(&sW[kk * 128 + j4]);
            float wv[4] = {w.x, w.y, w.z, w.w};
            #pragma unroll
            for (int ii = 0; ii < 8; ++ii)
                #pragma unroll
                for (int jj = 0; jj < 4; ++jj)
                    acc2[ii][jj] = fmaf(xv[ii], wv[jj], acc2[ii][jj]);
        }
    }
    #pragma unroll
    for (int ii = 0; ii < 8; ++ii) {
        int n = n0 + nBase + ii;
        if (n < N) {
            float4 s = *reinterpret_cast<const float4*>(&sS[(nBase + ii) * 128 + j4]);
            float4 o = make_float4(s.x + acc2[ii][0], s.y + acc2[ii][1],
                                   s.z + acc2[ii][2], s.w + acc2[ii][3]);
            *reinterpret_cast<float4*>(&out[(size_t)n * 128 + j4]) = o;
        }
    }
}

// ---------------------------------------------------------------------------
extern "C" void kernel_launch(void* const* d_in, const int* in_sizes, int n_in,
                              void* d_out, int out_size)
{
    const float* node_states = (const float*)d_in[0];
    const float* edge_feat   = (const float*)d_in[1];
    const int*   from_idx    = (const int*)d_in[2];
    const int*   to_idx      = (const int*)d_in[3];
    const float* W1  = (const float*)d_in[4];
    const float* b1  = (const float*)d_in[5];
    const float* W2  = (const float*)d_in[6];
    const float* b2  = (const float*)d_in[7];
    const float* RW1 = (const float*)d_in[8];
    const float* Rb1 = (const float*)d_in[9];
    const float* RW2 = (const float*)d_in[10];
    const float* Rb2 = (const float*)d_in[11];
    const float* Wn1 = (const float*)d_in[12];
    const float* bn1 = (const float*)d_in[13];
    const float* Wn2 = (const float*)d_in[14];
    const float* bn2 = (const float*)d_in[15];
    float* out = (float*)d_out;

    const int N = in_sizes[0] / 128;
    const int E = in_sizes[2];

    __half* w2p;
    cudaGetSymbolAddress((void**)&w2p, g_w2);

    cudaFuncSetAttribute(edge_mma_kernel, cudaFuncAttributeMaxDynamicSharedMemorySize, ESMEM);
    cudaFuncSetAttribute(precompute_y, cudaFuncAttributeMaxDynamicSharedMemorySize, 16384 * 4);
    cudaFuncSetAttribute(node_kernel, cudaFuncAttributeMaxDynamicSharedMemorySize, 49152 * 4);

    zero_agg_kernel<<<1024, 256>>>(N * 64);
    prep_w_kernel<<<256, 256>>>(W2,  w2p);
    prep_w_kernel<<<256, 256>>>(RW2, w2p + 65536);
    precompute_y<<<(N + 63) / 64, 256, 16384 * 4>>>(node_states, W1, RW1, b1, Rb1, N);
    edge_mma_kernel<<<152, 512, ESMEM>>>(edge_feat, from_idx, to_idx, W1,  b2,  0, E);
    edge_mma_kernel<<<152, 512, ESMEM>>>(edge_feat, from_idx, to_idx, RW1, Rb2, 1, E);
    node_kernel<<<(N + 63) / 64, 256, 49152 * 4>>>(node_states, Wn1, bn1, Wn2, bn2, out, N);
}

// round 17
// speedup vs baseline: 1.0224x; 1.0224x over previous
#include <cuda_runtime.h>
#include <cuda_fp16.h>
#include <cstdint>

#define MAX_N 50000

// ---------------- device scratch (no allocation allowed) -------------------
// g_Yh row layout (1024 halfs): [Y0 | Y3 | Y1 | Y2]
//   fwd edge: Y0[f] + Y1[t];  rev edge: Y2[t] + Y3[f]   (biases folded)
__device__ __half g_Yh[(size_t)MAX_N * 1024];  // 102.4 MB, fits L2
__device__ float  g_agg[(size_t)MAX_N * 256];  // [N][256] aggregation
__device__ __half g_w2[2][65536];              // [dir][n*256+k] fp16 W2

// ---------------- small asm helpers ----------------------------------------
__device__ __forceinline__ uint32_t smem_u32(const void* p) {
    uint32_t a;
    asm("{ .reg .u64 t; cvta.to.shared.u64 t, %1; cvt.u32.u64 %0, t; }" : "=r"(a) : "l"(p));
    return a;
}
__device__ __forceinline__ void cpa16(uint32_t dst, const void* src) {
    asm volatile("cp.async.cg.shared.global [%0], [%1], 16;" :: "r"(dst), "l"(src));
}
#define CP_COMMIT() asm volatile("cp.async.commit_group;" ::: "memory")
#define CP_WAIT(n)  asm volatile("cp.async.wait_group %0;" :: "n"(n) : "memory")

__device__ __forceinline__ void ldsm4(uint32_t* r, uint32_t addr) {
    asm volatile("ldmatrix.sync.aligned.m8n8.x4.shared.b16 {%0,%1,%2,%3}, [%4];"
                 : "=r"(r[0]), "=r"(r[1]), "=r"(r[2]), "=r"(r[3]) : "r"(addr));
}
__device__ __forceinline__ void ldsm2(uint32_t* r, uint32_t addr) {
    asm volatile("ldmatrix.sync.aligned.m8n8.x2.shared.b16 {%0,%1}, [%2];"
                 : "=r"(r[0]), "=r"(r[1]) : "r"(addr));
}
__device__ __forceinline__ void mma16816(float* c, const uint32_t* a, const uint32_t* b) {
    asm volatile("mma.sync.aligned.m16n8k16.row.col.f32.f16.f16.f32 "
                 "{%0,%1,%2,%3}, {%4,%5,%6,%7}, {%8,%9}, {%0,%1,%2,%3};"
                 : "+f"(c[0]), "+f"(c[1]), "+f"(c[2]), "+f"(c[3])
                 : "r"(a[0]), "r"(a[1]), "r"(a[2]), "r"(a[3]), "r"(b[0]), "r"(b[1]));
}
__device__ __forceinline__ void red2(float* p, float x, float y) {
    asm volatile("red.global.add.v2.f32 [%0], {%1,%2};" :: "l"(p), "f"(x), "f"(y) : "memory");
}
__device__ __forceinline__ uint32_t f2h(float a, float b) {
    __half2 h = __floats2half2_rn(a, b);
    return *reinterpret_cast<uint32_t*>(&h);
}
// combine: relu(a + b + ef*w) in half2
__device__ __forceinline__ uint32_t cmb(uint32_t a, uint32_t b, uint32_t w, __half2 ef2) {
    __half2 s = __hadd2(*reinterpret_cast<__half2*>(&a), *reinterpret_cast<__half2*>(&b));
    s = __hfma2(ef2, *reinterpret_cast<__half2*>(&w), s);
    __half2 z = __floats2half2_rn(0.f, 0.f);
    s = __hmax2(s, z);
    return *reinterpret_cast<uint32_t*>(&s);
}

// ---------------- persistent edge-kernel smem layout (bytes) ----------------
// Double-buffered hidden: SH(b) = b * 33,792   ([64 rows][264 halfs], stride 528B)
#define SHBUF(b) ((b) * 33792)
#define SW2   67584        // [256 n][264 halfs] W2 resident = 135,168B -> 202,752
#define SWEFH 202752       // 256 half -> 203,264
#define ESMEM 203264

// ---------------- prep: W2 transpose + fp16 round ---------------------------
__global__ void prep_w_kernel(const float* __restrict__ W, __half* __restrict__ oh) {
    int i = blockIdx.x * 256 + threadIdx.x;      // i = n*256 + k
    if (i >= 65536) return;
    int n = i >> 8, k = i & 255;
    oh[i] = __float2half_rn(W[k * 256 + n]);
}

__global__ void zero_agg_kernel(int n4) {
    float4* p = reinterpret_cast<float4*>(g_agg);
    int i = blockIdx.x * blockDim.x + threadIdx.x;
    int stride = gridDim.x * blockDim.x;
    float4 z = make_float4(0.f, 0.f, 0.f, 0.f);
    for (; i < n4; i += stride) p[i] = z;
}

// ---------------- node-level L1 precompute (exact fp32 FFMA -> fp16) --------
__global__ __launch_bounds__(256, 2)
void precompute_y(const float* __restrict__ ns,
                  const float* __restrict__ W1, const float* __restrict__ RW1,
                  const float* __restrict__ b1, const float* __restrict__ Rb1, int N)
{
    extern __shared__ float sm[];
    float* sS = sm;           // 64*128
    float* sW = sm + 8192;    // 32*256
    const int tid = threadIdx.x;
    const int n0 = blockIdx.x * 64;

    for (int t = tid; t < 64 * 32; t += 256) {
        int n = t >> 5, c = t & 31;
        float4 v = make_float4(0.f, 0.f, 0.f, 0.f);
        if (n0 + n < N)
            v = reinterpret_cast<const float4*>(ns)[(size_t)(n0 + n) * 32 + c];
        reinterpret_cast<float4*>(sS)[t] = v;
    }

    const int wg = tid >> 5, lane = tid & 31;
    const int nb = wg * 8, j0 = lane * 8;

    for (int q = 0; q < 4; ++q) {
        const float* Wsrc = (q < 2) ? W1 : RW1;
        const int rowoff = (q & 1) * 128;
        const int seg = (q == 0) ? 0 : (q == 1) ? 2 : (q == 2) ? 3 : 1;
        float acc[8][8];
        #pragma unroll
        for (int jj = 0; jj < 8; ++jj) {
            float bv = (q == 1) ? b1[j0 + jj] : ((q == 3) ? Rb1[j0 + jj] : 0.f);
            #pragma unroll
            for (int ii = 0; ii < 8; ++ii) acc[ii][jj] = bv;
        }
        for (int kt = 0; kt < 4; ++kt) {
            __syncthreads();
            {
                const float4* src = reinterpret_cast<const float4*>(Wsrc + (rowoff + kt * 32) * 256);
                float4* dw = reinterpret_cast<float4*>(sW);
                #pragma unroll
                for (int t0 = 0; t0 < 8; ++t0) dw[tid + t0 * 256] = src[tid + t0 * 256];
            }
            __syncthreads();
            #pragma unroll 8
            for (int kk = 0; kk < 32; ++kk) {
                float xv[8];
                #pragma unroll
                for (int ii = 0; ii < 8; ++ii) xv[ii] = sS[(nb + ii) * 128 + kt * 32 + kk];
                float4 w0 = *reinterpret_cast<const float4*>(&sW[kk * 256 + j0]);
                float4 w1 = *reinterpret_cast<const float4*>(&sW[kk * 256 + j0 + 4]);
                float wv[8] = {w0.x, w0.y, w0.z, w0.w, w1.x, w1.y, w1.z, w1.w};
                #pragma unroll
                for (int ii = 0; ii < 8; ++ii)
                    #pragma unroll
                    for (int jj = 0; jj < 8; ++jj)
                        acc[ii][jj] = fmaf(xv[ii], wv[jj], acc[ii][jj]);
            }
        }
        #pragma unroll
        for (int ii = 0; ii < 8; ++ii) {
            int n = n0 + nb + ii;
            if (n < N) {
                uint4 pk;
                pk.x = f2h(acc[ii][0], acc[ii][1]);
                pk.y = f2h(acc[ii][2], acc[ii][3]);
                pk.z = f2h(acc[ii][4], acc[ii][5]);
                pk.w = f2h(acc[ii][6], acc[ii][7]);
                *reinterpret_cast<uint4*>(g_Yh + (size_t)n * 1024 + seg * 256 + j0) = pk;
            }
        }
    }
}

// ---------------- persistent warp-specialized edge kernel -------------------
// Warps 0-7: consumers (MMA on sH[t&1] + scatter).  Warps 8-15: producers
// (combine tile t+1 -> sH[(t+1)&1]).  ONE __syncthreads per tile.
__global__ __launch_bounds__(512, 1)
void edge_mma_kernel(const float* __restrict__ ef,
                     const int* __restrict__ fidx, const int* __restrict__ tidx,
                     const float* __restrict__ W1base,   // W1 or RW1 (ef column)
                     const float* __restrict__ bias2,
                     int dir, int E)
{
    extern __shared__ float smf[];
    char* smc = reinterpret_cast<char*>(smf);
    const uint32_t smb = smem_u32(smf);
    const int tid = threadIdx.x;
    const int wid = tid >> 5, lane = tid & 31;
    const bool producer = (wid >= 8);

    __half* sWefH = reinterpret_cast<__half*>(smc + SWEFH);

    // ---- one-time: W2[dir] -> smem (256 n-rows x 256 halfs, stride 528B) ---
    {
        const __half* gw = g_w2[dir];
        #pragma unroll
        for (int t0 = 0; t0 < 16; ++t0) {
            int idx = t0 * 512 + tid;            // 8192 x 16B
            int n = idx >> 5, seg = idx & 31;
            cpa16(smb + SW2 + (uint32_t)(n * 528 + seg * 16), gw + n * 256 + seg * 8);
        }
        CP_COMMIT();
        if (tid < 256) sWefH[tid] = __float2half_rn(W1base[65536 + tid]);
        CP_WAIT(0);
        __syncthreads();
    }

    const int nTiles = (E + 63) >> 6;

    // ---------------- consumer state ----------------------------------------
    const int wm = wid & 1, wn = wid >> 1;       // 2 m-warps x 4 n-warps (wid<8)
    const int m0 = wm * 32, n0 = wn * 64;        // warp tile 32 x 64
    const int rA = (lane & 7) + ((lane >> 3) & 1) * 8;
    const int cAo = (lane >> 4) * 8;
    const uint32_t aOffA = (uint32_t)((m0 + rA) * 528 + cAo * 2);
    const uint32_t bB = smb + SW2 +
        (uint32_t)((n0 + (lane & 7)) * 528 + ((lane >> 3) & 1) * 16);
    const int r0 = m0 + (lane >> 2);
    float bv[8][2];
    if (!producer) {
        #pragma unroll
        for (int nf = 0; nf < 8; ++nf) {
            int cc = n0 + nf * 8 + (lane & 3) * 2;
            bv[nf][0] = bias2[cc];
            bv[nf][1] = bias2[cc + 1];
        }
    }

    // ---------------- producer state ----------------------------------------
    const int ptid = tid - 256;                  // 0..255 for producers
    const int crow = ptid >> 2, cq = ptid & 3;   // 64 rows x 4 quarters
    const uint4* W4 = reinterpret_cast<const uint4*>(sWefH + (cq & 3) * 64);

    // producer combine of one tile into buffer b
    auto combine = [&](int tile, int b) {
        const int e0 = tile * 64;
        int ce = e0 + crow; if (ce >= E) ce = E - 1;
        const int cf = fidx[ce], ct = tidx[ce];
        const __half* Ap;
        const __half* Bp;
        if (dir == 0) {   // fwd: Y0[f] + Y1[t]
            Ap = g_Yh + (size_t)cf * 1024 + cq * 64;
            Bp = g_Yh + (size_t)ct * 1024 + 512 + cq * 64;
        } else {          // rev: Y2[t] + Y3[f]
            Ap = g_Yh + (size_t)ct * 1024 + 768 + cq * 64;
            Bp = g_Yh + (size_t)cf * 1024 + 256 + cq * 64;
        }
        const __half2 ef2 = __float2half2_rn(ef[ce]);
        const uint4* A4 = reinterpret_cast<const uint4*>(Ap);
        const uint4* B4 = reinterpret_cast<const uint4*>(Bp);
        char* dstb = smc + SHBUF(b) + crow * 528 + (cq * 64) * 2;
        #pragma unroll
        for (int i = 0; i < 8; ++i) {
            uint4 ua = A4[i], ub = B4[i], uw = W4[i];
            uint4 pk;
            pk.x = cmb(ua.x, ub.x, uw.x, ef2);
            pk.y = cmb(ua.y, ub.y, uw.y, ef2);
            pk.z = cmb(ua.z, ub.z, uw.z, ef2);
            pk.w = cmb(ua.w, ub.w, uw.w, ef2);
            *reinterpret_cast<uint4*>(dstb + i * 16) = pk;
        }
    };

    // prologue: producers fill buffer 0 with this CTA's first tile
    if (producer && blockIdx.x < nTiles) combine(blockIdx.x, 0);
    __syncthreads();

    for (int t = 0;; ++t) {
        const int tile = blockIdx.x + t * gridDim.x;
        if (tile >= nTiles) break;
        const int b = t & 1;

        if (!producer) {
            // ---- MMA on sH[b] (sync-free: W2 resident, sH read-only) --------
            float acc0[8][4], acc1[8][4];
            #pragma unroll
            for (int nf = 0; nf < 8; ++nf) {
                acc0[nf][0] = bv[nf][0]; acc0[nf][1] = bv[nf][1];
                acc0[nf][2] = bv[nf][0]; acc0[nf][3] = bv[nf][1];
                acc1[nf][0] = bv[nf][0]; acc1[nf][1] = bv[nf][1];
                acc1[nf][2] = bv[nf][0]; acc1[nf][3] = bv[nf][1];
            }
            const uint32_t aB0 = smb + SHBUF(b) + aOffA;
            const uint32_t aB1 = aB0 + 16 * 528;
            #pragma unroll 4
            for (int ks = 0; ks < 16; ++ks) {
                uint32_t A0[4], A1[4];
                ldsm4(A0, aB0 + ks * 32);
                ldsm4(A1, aB1 + ks * 32);
                const uint32_t wk = bB + ks * 32;
                #pragma unroll
                for (int nf = 0; nf < 8; ++nf) {
                    uint32_t Bh[2];
                    ldsm2(Bh, wk + nf * 4224);    // +8 n-rows = 8*528B
                    mma16816(acc0[nf], A0, Bh);
                    mma16816(acc1[nf], A1, Bh);
                }
            }
            // ---- scatter (never touches sH) ---------------------------------
            const int* iD = dir ? fidx : tidx;
            const int e0 = tile * 64;
            const int e00 = e0 + r0;
            const int e08 = e00 + 8, e16 = e00 + 16, e24 = e00 + 24;
            const int d00 = (e00 < E) ? iD[e00] : 0;
            const int d08 = (e08 < E) ? iD[e08] : 0;
            const int d16 = (e16 < E) ? iD[e16] : 0;
            const int d24 = (e24 < E) ? iD[e24] : 0;
            float* p00 = g_agg + (size_t)d00 * 256;
            float* p08 = g_agg + (size_t)d08 * 256;
            float* p16 = g_agg + (size_t)d16 * 256;
            float* p24 = g_agg + (size_t)d24 * 256;
            #pragma unroll
            for (int nf = 0; nf < 8; ++nf) {
                int cc = n0 + nf * 8 + (lane & 3) * 2;
                if (e00 < E) red2(p00 + cc, acc0[nf][0], acc0[nf][1]);
                if (e08 < E) red2(p08 + cc, acc0[nf][2], acc0[nf][3]);
                if (e16 < E) red2(p16 + cc, acc1[nf][0], acc1[nf][1]);
                if (e24 < E) red2(p24 + cc, acc1[nf][2], acc1[nf][3]);
            }
        } else {
            // ---- combine next tile into the other buffer --------------------
            const int ntile = blockIdx.x + (t + 1) * gridDim.x;
            if (ntile < nTiles) combine(ntile, b ^ 1);
        }
        __syncthreads();    // buffer handoff (consumers done with b; producers filled b^1)
    }
}

// ---------------- node update MLP + residual (FFMA, 256 thr, 2 CTA/SM) -----
__global__ __launch_bounds__(256, 2)
void node_kernel(const float* __restrict__ node_states,
                 const float* __restrict__ Wn1, const float* __restrict__ bn1,
                 const float* __restrict__ Wn2, const float* __restrict__ bn2,
                 float* __restrict__ out, int N)
{
    extern __shared__ float sm[];
    float* sA = sm;            // 64*256
    float* sS = sm + 16384;    // 64*128
    float* sH = sm + 24576;    // 64*256
    float* sW = sm + 40960;    // 32*256

    const int tid = threadIdx.x;
    const int n0  = blockIdx.x * 64;

    for (int t = tid; t < 64 * 64; t += 256) {
        int n = t >> 6, c = t & 63;
        float4 v = make_float4(0.f, 0.f, 0.f, 0.f);
        if (n0 + n < N)
            v = reinterpret_cast<const float4*>(g_agg)[(size_t)(n0 + n) * 64 + c];
        reinterpret_cast<float4*>(sA)[t] = v;
    }
    for (int t = tid; t < 64 * 32; t += 256) {
        int n = t >> 5, c = t & 31;
        float4 v = make_float4(0.f, 0.f, 0.f, 0.f);
        if (n0 + n < N)
            v = reinterpret_cast<const float4*>(node_states)[(size_t)(n0 + n) * 32 + c];
        reinterpret_cast<float4*>(sS)[t] = v;
    }
    __syncthreads();

    const int wg = tid >> 5, lane = tid & 31;
    const int nBase = wg * 8, j0 = lane * 8;

    float acc[8][8];
    #pragma unroll
    for (int jj = 0; jj < 8; ++jj) {
        float bv = bn1[j0 + jj];
        #pragma unroll
        for (int ii = 0; ii < 8; ++ii) acc[ii][jj] = bv;
    }
    for (int kt = 0; kt < 12; ++kt) {
        __syncthreads();
        {
            const float4* src = reinterpret_cast<const float4*>(Wn1 + kt * 32 * 256);
            float4* dw = reinterpret_cast<float4*>(sW);
            #pragma unroll
            for (int t0 = 0; t0 < 8; ++t0) dw[tid + t0 * 256] = src[tid + t0 * 256];
        }
        __syncthreads();
        const float* Xb; int strd;
        if (kt < 8) { Xb = sA + kt * 32;       strd = 256; }
        else        { Xb = sS + (kt - 8) * 32; strd = 128; }
        #pragma unroll 8
        for (int kk = 0; kk < 32; ++kk) {
            float xv[8];
            #pragma unroll
            for (int ii = 0; ii < 8; ++ii) xv[ii] = Xb[(nBase + ii) * strd + kk];
            float4 w0 = *reinterpret_cast<const float4*>(&sW[kk * 256 + j0]);
            float4 w1 = *reinterpret_cast<const float4*>(&sW[kk * 256 + j0 + 4]);
            float wv[8] = {w0.x, w0.y, w0.z, w0.w, w1.x, w1.y, w1.z, w1.w};
            #pragma unroll
            for (int ii = 0; ii < 8; ++ii)
                #pragma unroll
                for (int jj = 0; jj < 8; ++jj)
                    acc[ii][jj] = fmaf(xv[ii], wv[jj], acc[ii][jj]);
        }
    }
    #pragma unroll
    for (int ii = 0; ii < 8; ++ii) {
        float4 h0 = make_float4(fmaxf(acc[ii][0], 0.f), fmaxf(acc[ii][1], 0.f),
                                fmaxf(acc[ii][2], 0.f), fmaxf(acc[ii][3], 0.f));
        float4 h1 = make_float4(fmaxf(acc[ii][4], 0.f), fmaxf(acc[ii][5], 0.f),
                                fmaxf(acc[ii][6], 0.f), fmaxf(acc[ii][7], 0.f));
        *reinterpret_cast<float4*>(&sH[(nBase + ii) * 256 + j0])     = h0;
        *reinterpret_cast<float4*>(&sH[(nBase + ii) * 256 + j0 + 4]) = h1;
    }

    const int j4 = lane * 4;
    float acc2[8][4];
    #pragma unroll
    for (int jj = 0; jj < 4; ++jj) {
        float bv = bn2[j4 + jj];
        #pragma unroll
        for (int ii = 0; ii < 8; ++ii) acc2[ii][jj] = bv;
    }
    for (int kt = 0; kt < 8; ++kt) {
        __syncthreads();
        {
            const float4* src = reinterpret_cast<const float4*>(Wn2 + kt * 32 * 128);
            float4* dw = reinterpret_cast<float4*>(sW);
            #pragma unroll
            for (int t0 = 0; t0 < 4; ++t0) dw[tid + t0 * 256] = src[tid + t0 * 256];
        }
        __syncthreads();
        #pragma unroll 8
        for (int kk = 0; kk < 32; ++kk) {
            float xv[8];
            #pragma unroll
            for (int ii = 0; ii < 8; ++ii) xv[ii] = sH[(nBase + ii) * 256 + kt * 32 + kk];
            float4 w = *reinterpret_cast<const float4*>(&sW[kk * 128 + j4]);
            float wv[4] = {w.x, w.y, w.z, w.w};
            #pragma unroll
            for (int ii = 0; ii < 8; ++ii)
                #pragma unroll
                for (int jj = 0; jj < 4; ++jj)
                    acc2[ii][jj] = fmaf(xv[ii], wv[jj], acc2[ii][jj]);
        }
    }
    #pragma unroll
    for (int ii = 0; ii < 8; ++ii) {
        int n = n0 + nBase + ii;
        if (n < N) {
            float4 s = *reinterpret_cast<const float4*>(&sS[(nBase + ii) * 128 + j4]);
            float4 o = make_float4(s.x + acc2[ii][0], s.y + acc2[ii][1],
                                   s.z + acc2[ii][2], s.w + acc2[ii][3]);
            *reinterpret_cast<float4*>(&out[(size_t)n * 128 + j4]) = o;
        }
    }
}

// ---------------------------------------------------------------------------
extern "C" void kernel_launch(void* const* d_in, const int* in_sizes, int n_in,
                              void* d_out, int out_size)
{
    const float* node_states = (const float*)d_in[0];
    const float* edge_feat   = (const float*)d_in[1];
    const int*   from_idx    = (const int*)d_in[2];
    const int*   to_idx      = (const int*)d_in[3];
    const float* W1  = (const float*)d_in[4];
    const float* b1  = (const float*)d_in[5];
    const float* W2  = (const float*)d_in[6];
    const float* b2  = (const float*)d_in[7];
    const float* RW1 = (const float*)d_in[8];
    const float* Rb1 = (const float*)d_in[9];
    const float* RW2 = (const float*)d_in[10];
    const float* Rb2 = (const float*)d_in[11];
    const float* Wn1 = (const float*)d_in[12];
    const float* bn1 = (const float*)d_in[13];
    const float* Wn2 = (const float*)d_in[14];
    const float* bn2 = (const float*)d_in[15];
    float* out = (float*)d_out;

    const int N = in_sizes[0] / 128;
    const int E = in_sizes[2];

    __half* w2p;
    cudaGetSymbolAddress((void**)&w2p, g_w2);

    cudaFuncSetAttribute(edge_mma_kernel, cudaFuncAttributeMaxDynamicSharedMemorySize, ESMEM);
    cudaFuncSetAttribute(precompute_y, cudaFuncAttributeMaxDynamicSharedMemorySize, 16384 * 4);
    cudaFuncSetAttribute(node_kernel, cudaFuncAttributeMaxDynamicSharedMemorySize, 49152 * 4);

    zero_agg_kernel<<<1024, 256>>>(N * 64);
    prep_w_kernel<<<256, 256>>>(W2,  w2p);
    prep_w_kernel<<<256, 256>>>(RW2, w2p + 65536);
    precompute_y<<<(N + 63) / 64, 256, 16384 * 4>>>(node_states, W1, RW1, b1, Rb1, N);
    edge_mma_kernel<<<152, 512, ESMEM>>>(edge_feat, from_idx, to_idx, W1,  b2,  0, E);
    edge_mma_kernel<<<152, 512, ESMEM>>>(edge_feat, from_idx, to_idx, RW1, Rb2, 1, E);
    node_kernel<<<(N + 63) / 64, 256, 49152 * 4>>>(node_states, Wn1, bn1, Wn2, bn2, out, N);
}